// round 4
// baseline (speedup 1.0000x reference)
#include <cuda_runtime.h>
#include <cstdint>

#define B_ 4
#define L_ 2048
#define D_ 512
#define H_ 8
#define E_ 64

// Projected Q/K/V scratch, [B,H,L,E] (each (b,h) slice is contiguous [L,E]).
__device__ __align__(256) float g_q[B_ * H_ * L_ * E_];
__device__ __align__(256) float g_k[B_ * H_ * L_ * E_];
__device__ __align__(256) float g_v[B_ * H_ * L_ * E_];

// ---------------------------------------------------------------------------
// helpers
// ---------------------------------------------------------------------------
__device__ __forceinline__ uint32_t smem_u32(const void* p) {
    uint32_t a;
    asm("{ .reg .u64 t; cvta.to.shared.u64 t, %1; cvt.u32.u64 %0, t; }"
        : "=r"(a) : "l"(p));
    return a;
}

// D = A(16x8,row) * B(8x8,col) + D, tf32 inputs (raw f32 bits, HW truncates)
__device__ __forceinline__ void mma_tf32(float* d, const uint32_t* a, const uint32_t* b) {
    asm volatile(
        "mma.sync.aligned.m16n8k8.row.col.f32.tf32.tf32.f32 "
        "{%0,%1,%2,%3}, {%4,%5,%6,%7}, {%8,%9}, {%0,%1,%2,%3};"
        : "+f"(d[0]), "+f"(d[1]), "+f"(d[2]), "+f"(d[3])
        : "r"(a[0]), "r"(a[1]), "r"(a[2]), "r"(a[3]), "r"(b[0]), "r"(b[1]));
}

// 3xTF32 split: x = hi + lo, hi exactly representable in tf32.
__device__ __forceinline__ void split2(float x, uint32_t& hi, uint32_t& lo) {
    uint32_t xb = __float_as_uint(x);
    hi = xb & 0xFFFFE000u;
    lo = __float_as_uint(x - __uint_as_float(hi));
}

__device__ __forceinline__ void cp16(uint32_t dst, const void* src) {
    asm volatile("cp.async.cg.shared.global [%0], [%1], 16;"
                 :: "r"(dst), "l"(src) : "memory");
}
#define CP_COMMIT() asm volatile("cp.async.commit_group;" ::: "memory")
#define CP_WAIT(n)  asm volatile("cp.async.wait_group %0;" :: "n"(n) : "memory")

// ---------------------------------------------------------------------------
// Kernel 1a: Q/K projection (1x tf32).  CTA 128x128, 8 warps (2M x 4N),
// K=512 in BK=32 chunks, cp.async double buffer.  grid (64, 4, 2), 256 thr.
// SMEM: Xs[2][128][36], Ws[2][32][136]
// ---------------------------------------------------------------------------
static constexpr int PJ_XS = 128 * 36;
static constexpr int PJ_WS = 32 * 136;
static constexpr int PJ_SMEM = (2 * PJ_XS + 2 * PJ_WS) * 4;   // 71680 B

__global__ void __launch_bounds__(256) proj_mma(
    const float* __restrict__ X0, const float* __restrict__ X1,
    const float* __restrict__ W0, const float* __restrict__ W1,
    const float* __restrict__ b0, const float* __restrict__ b1)
{
    extern __shared__ float smf[];
    float* Xs = smf;
    float* Ws = smf + 2 * PJ_XS;
    uint32_t sX = smem_u32(Xs), sW = smem_u32(Ws);

    int z = blockIdx.z;
    const float* X = z ? X1 : X0;
    const float* W = z ? W1 : W0;
    const float* bias = z ? b1 : b0;
    float* dst = z ? g_k : g_q;

    int t = threadIdx.x;
    int lane = t & 31, wid = t >> 5;
    int gid = lane >> 2, tg = lane & 3;
    int warpM = wid >> 2, warpN = wid & 3;
    int m0 = blockIdx.x * 128, n0 = blockIdx.y * 128;

    float acc[4][4][4] = {};

    auto stage = [&](int kt, int buf) {
        int k0 = kt * 32;
#pragma unroll
        for (int i = 0; i < 4; i++) {
            int idx = t + i * 256;
            int row = idx >> 3, cc = (idx & 7) * 4;
            cp16(sX + (buf * PJ_XS + row * 36 + cc) * 4,
                 X + (size_t)(m0 + row) * D_ + k0 + cc);
        }
#pragma unroll
        for (int i = 0; i < 4; i++) {
            int idx = t + i * 256;
            int row = idx >> 5, cc = (idx & 31) * 4;
            cp16(sW + (buf * PJ_WS + row * 136 + cc) * 4,
                 W + (size_t)(k0 + row) * D_ + n0 + cc);
        }
    };

    stage(0, 0); CP_COMMIT();
    const int NIT = D_ / 32;                 // 16
    for (int kt = 0; kt < NIT; kt++) {
        int p = kt & 1;
        if (kt + 1 < NIT) { stage(kt + 1, p ^ 1); CP_COMMIT(); CP_WAIT(1); }
        else              { CP_WAIT(0); }
        __syncthreads();

        const float* Ab = Xs + p * PJ_XS;
        const float* Bb = Ws + p * PJ_WS;
#pragma unroll
        for (int ks = 0; ks < 4; ks++) {
            int k0 = ks * 8;
            uint32_t a[4][4], b[4][2];
#pragma unroll
            for (int mt = 0; mt < 4; mt++) {
                const float* pa = Ab + (warpM * 64 + mt * 16 + gid) * 36 + k0 + tg;
                a[mt][0] = __float_as_uint(pa[0]);
                a[mt][1] = __float_as_uint(pa[8 * 36]);
                a[mt][2] = __float_as_uint(pa[4]);
                a[mt][3] = __float_as_uint(pa[8 * 36 + 4]);
            }
#pragma unroll
            for (int nt = 0; nt < 4; nt++) {
                const float* pb = Bb + (k0 + tg) * 136 + warpN * 32 + nt * 8 + gid;
                b[nt][0] = __float_as_uint(pb[0]);
                b[nt][1] = __float_as_uint(pb[4 * 136]);
            }
#pragma unroll
            for (int mt = 0; mt < 4; mt++)
#pragma unroll
                for (int nt = 0; nt < 4; nt++)
                    mma_tf32(acc[mt][nt], a[mt], b[nt]);
        }
        __syncthreads();
    }

#pragma unroll
    for (int mt = 0; mt < 4; mt++) {
        int m = m0 + warpM * 64 + mt * 16 + gid;
        int bb = m >> 11;
        int l  = m & (L_ - 1);
#pragma unroll
        for (int nt = 0; nt < 4; nt++) {
            int n = n0 + warpN * 32 + nt * 8 + tg * 2;
            int h = n >> 6, e = n & 63;
            float2 bi = *reinterpret_cast<const float2*>(bias + n);
            *reinterpret_cast<float2*>(dst + (((size_t)(bb * H_ + h)) * L_ + l) * E_ + e) =
                make_float2(acc[mt][nt][0] + bi.x, acc[mt][nt][1] + bi.y);
            *reinterpret_cast<float2*>(dst + (((size_t)(bb * H_ + h)) * L_ + l + 8) * E_ + e) =
                make_float2(acc[mt][nt][2] + bi.x, acc[mt][nt][3] + bi.y);
        }
    }
}

// ---------------------------------------------------------------------------
// Kernel 1b: V projection, 3xTF32.  CTA 128x64, 8 warps (4M x 2N),
// K=512 in BK=32 chunks, 3-stage cp.async pipeline.  grid (64, 8), 256 thr.
// SMEM: Xs[3][128][36], Ws[3][32][72]
// ---------------------------------------------------------------------------
static constexpr int PV_XS = 128 * 36;
static constexpr int PV_WS = 32 * 72;
static constexpr int PV_SMEM = (3 * PV_XS + 3 * PV_WS) * 4;   // 82944 B

__global__ void __launch_bounds__(256, 2) projv_mma3(
    const float* __restrict__ X, const float* __restrict__ W,
    const float* __restrict__ bias)
{
    extern __shared__ float smf[];
    float* Xs = smf;
    float* Ws = smf + 3 * PV_XS;
    uint32_t sX = smem_u32(Xs), sW = smem_u32(Ws);

    int t = threadIdx.x;
    int lane = t & 31, wid = t >> 5;
    int gid = lane >> 2, tg = lane & 3;
    int warpM = wid >> 1, warpN = wid & 1;
    int m0 = blockIdx.x * 128, n0 = blockIdx.y * 64;

    float acc[2][4][4] = {};

    auto stage = [&](int kt, int buf) {
        int k0 = kt * 32;
#pragma unroll
        for (int i = 0; i < 4; i++) {
            int idx = t + i * 256;            // X 128x32
            int row = idx >> 3, cc = (idx & 7) * 4;
            cp16(sX + (buf * PV_XS + row * 36 + cc) * 4,
                 X + (size_t)(m0 + row) * D_ + k0 + cc);
        }
#pragma unroll
        for (int i = 0; i < 2; i++) {
            int idx = t + i * 256;            // W 32x64
            int row = idx >> 4, cc = (idx & 15) * 4;
            cp16(sW + (buf * PV_WS + row * 72 + cc) * 4,
                 W + (size_t)(k0 + row) * D_ + n0 + cc);
        }
    };

    const int NIT = D_ / 32;                  // 16
    stage(0, 0); CP_COMMIT();
    stage(1, 1); CP_COMMIT();
    for (int kt = 0; kt < NIT; kt++) {
        __syncthreads();
        if (kt + 2 < NIT) { stage(kt + 2, (kt + 2) % 3); CP_COMMIT(); CP_WAIT(2); }
        else if (kt + 1 < NIT) { CP_WAIT(1); }
        else { CP_WAIT(0); }
        __syncthreads();

        int p = kt % 3;
        const float* Ab = Xs + p * PV_XS;
        const float* Bb = Ws + p * PV_WS;
#pragma unroll
        for (int ks = 0; ks < 4; ks++) {
            int k0 = ks * 8;
            uint32_t ah[2][4], al[2][4], bh[4][2], bl[4][2];
#pragma unroll
            for (int mt = 0; mt < 2; mt++) {
                const float* pa = Ab + (warpM * 32 + mt * 16 + gid) * 36 + k0 + tg;
                split2(pa[0],           ah[mt][0], al[mt][0]);
                split2(pa[8 * 36],      ah[mt][1], al[mt][1]);
                split2(pa[4],           ah[mt][2], al[mt][2]);
                split2(pa[8 * 36 + 4],  ah[mt][3], al[mt][3]);
            }
#pragma unroll
            for (int nt = 0; nt < 4; nt++) {
                const float* pb = Bb + (k0 + tg) * 72 + warpN * 32 + nt * 8 + gid;
                split2(pb[0],      bh[nt][0], bl[nt][0]);
                split2(pb[4 * 72], bh[nt][1], bl[nt][1]);
            }
#pragma unroll
            for (int mt = 0; mt < 2; mt++)
#pragma unroll
                for (int nt = 0; nt < 4; nt++) {
                    mma_tf32(acc[mt][nt], al[mt], bh[nt]);
                    mma_tf32(acc[mt][nt], ah[mt], bl[nt]);
                    mma_tf32(acc[mt][nt], ah[mt], bh[nt]);
                }
        }
    }

#pragma unroll
    for (int mt = 0; mt < 2; mt++) {
        int m = m0 + warpM * 32 + mt * 16 + gid;
        int bb = m >> 11;
        int l  = m & (L_ - 1);
#pragma unroll
        for (int nt = 0; nt < 4; nt++) {
            int n = n0 + warpN * 32 + nt * 8 + tg * 2;
            int h = n >> 6, e = n & 63;
            float2 bi = *reinterpret_cast<const float2*>(bias + n);
            *reinterpret_cast<float2*>(g_v + (((size_t)(bb * H_ + h)) * L_ + l) * E_ + e) =
                make_float2(acc[mt][nt][0] + bi.x, acc[mt][nt][1] + bi.y);
            *reinterpret_cast<float2*>(g_v + (((size_t)(bb * H_ + h)) * L_ + l + 8) * E_ + e) =
                make_float2(acc[mt][nt][2] + bi.x, acc[mt][nt][3] + bi.y);
        }
    }
}

// ---------------------------------------------------------------------------
// Kernel 2: scores via mma.sync (1x tf32).  S = scale * Q K^T per (b,h).
// CTA 128x128 output tile, full K=64 resident.  grid (16,16,32), 256 threads.
// ---------------------------------------------------------------------------
static constexpr int S_SMEM = 2 * 128 * 68 * 4;   // 69632 B

__global__ void __launch_bounds__(256) scores_mma(float* __restrict__ attn)
{
    extern __shared__ float smf[];
    float* Qs = smf;
    float* Ks = smf + 128 * 68;

    int t = threadIdx.x;
    int lane = t & 31, wid = t >> 5;
    int gid = lane >> 2, tg = lane & 3;
    int warpM = wid >> 2, warpN = wid & 3;
    int m0 = blockIdx.x * 128, n0 = blockIdx.y * 128, bh = blockIdx.z;

    const float* Q = g_q + (size_t)bh * L_ * E_;
    const float* K = g_k + (size_t)bh * L_ * E_;
    float* S = attn + (size_t)bh * L_ * L_;

#pragma unroll
    for (int i = 0; i < 8; i++) {
        int idx = t + i * 256;
        int row = idx >> 4, cc = (idx & 15) * 4;
        *reinterpret_cast<float4*>(Qs + row * 68 + cc) =
            *reinterpret_cast<const float4*>(Q + (size_t)(m0 + row) * E_ + cc);
        *reinterpret_cast<float4*>(Ks + row * 68 + cc) =
            *reinterpret_cast<const float4*>(K + (size_t)(n0 + row) * E_ + cc);
    }
    __syncthreads();

    float acc[4][4][4] = {};
#pragma unroll
    for (int ks = 0; ks < 8; ks++) {
        int k0 = ks * 8;
        uint32_t a[4][4], b[4][2];
#pragma unroll
        for (int mt = 0; mt < 4; mt++) {
            const float* pa = Qs + (warpM * 64 + mt * 16 + gid) * 68 + k0 + tg;
            a[mt][0] = __float_as_uint(pa[0]);
            a[mt][1] = __float_as_uint(pa[8 * 68]);
            a[mt][2] = __float_as_uint(pa[4]);
            a[mt][3] = __float_as_uint(pa[8 * 68 + 4]);
        }
#pragma unroll
        for (int nt = 0; nt < 4; nt++) {
            const float* pb = Ks + (warpN * 32 + nt * 8 + gid) * 68 + k0 + tg;
            b[nt][0] = __float_as_uint(pb[0]);
            b[nt][1] = __float_as_uint(pb[4]);
        }
#pragma unroll
        for (int mt = 0; mt < 4; mt++)
#pragma unroll
            for (int nt = 0; nt < 4; nt++)
                mma_tf32(acc[mt][nt], a[mt], b[nt]);
    }

    const float scale = 0.125f;
#pragma unroll
    for (int mt = 0; mt < 4; mt++) {
        int r = m0 + warpM * 64 + mt * 16 + gid;
#pragma unroll
        for (int nt = 0; nt < 4; nt++) {
            int cc = n0 + warpN * 32 + nt * 8 + tg * 2;
            *reinterpret_cast<float2*>(S + (size_t)r * L_ + cc) =
                make_float2(acc[mt][nt][0] * scale, acc[mt][nt][1] * scale);
            *reinterpret_cast<float2*>(S + (size_t)(r + 8) * L_ + cc) =
                make_float2(acc[mt][nt][2] * scale, acc[mt][nt][3] * scale);
        }
    }
}

// ---------------------------------------------------------------------------
// Kernel 3: row softmax in place.  grid 65536, 256 threads.
// ---------------------------------------------------------------------------
__global__ void softmax_kernel(float* __restrict__ attn)
{
    float* p = attn + (size_t)blockIdx.x * L_;
    int t = threadIdx.x, w = t >> 5, lane = t & 31;

    float4* pv = reinterpret_cast<float4*>(p);
    float4 a = pv[t];
    float4 b = pv[t + 256];

    float m = fmaxf(fmaxf(fmaxf(a.x, a.y), fmaxf(a.z, a.w)),
                    fmaxf(fmaxf(b.x, b.y), fmaxf(b.z, b.w)));
#pragma unroll
    for (int o = 16; o; o >>= 1) m = fmaxf(m, __shfl_xor_sync(0xffffffffu, m, o));

    __shared__ float smax[8];
    __shared__ float ssum[8];
    if (lane == 0) smax[w] = m;
    __syncthreads();
    m = smax[0];
#pragma unroll
    for (int i = 1; i < 8; i++) m = fmaxf(m, smax[i]);

    a.x = __expf(a.x - m); a.y = __expf(a.y - m);
    a.z = __expf(a.z - m); a.w = __expf(a.w - m);
    b.x = __expf(b.x - m); b.y = __expf(b.y - m);
    b.z = __expf(b.z - m); b.w = __expf(b.w - m);

    float s = a.x + a.y + a.z + a.w + b.x + b.y + b.z + b.w;
#pragma unroll
    for (int o = 16; o; o >>= 1) s += __shfl_xor_sync(0xffffffffu, s, o);
    if (lane == 0) ssum[w] = s;
    __syncthreads();
    s = ssum[0];
#pragma unroll
    for (int i = 1; i < 8; i++) s += ssum[i];

    float inv = 1.0f / s;
    a.x *= inv; a.y *= inv; a.z *= inv; a.w *= inv;
    b.x *= inv; b.y *= inv; b.z *= inv; b.w *= inv;
    pv[t] = a;
    pv[t + 256] = b;
}

// ---------------------------------------------------------------------------
// Kernel 4: AV via 3xTF32 mma.sync.  out = attn @ V per (b,h).
// CTA 128x64 output, K=2048 in BK=32 chunks, 3-stage cp.async pipeline.
// 8 warps (4M x 2N).  grid (16,1,32), 256 threads.
// SMEM: As[3][128][36], Bs[3][32][72]
// ---------------------------------------------------------------------------
static constexpr int AV_AS = 128 * 36;
static constexpr int AV_BS = 32 * 72;
static constexpr int AV_SMEM = (3 * AV_AS + 3 * AV_BS) * 4;   // 82944 B

__global__ void __launch_bounds__(256, 2) av_mma3(const float* __restrict__ attn,
                                                  float* __restrict__ out)
{
    extern __shared__ float smf[];
    float* As = smf;
    float* Bs = smf + 3 * AV_AS;
    uint32_t sA = smem_u32(As), sB = smem_u32(Bs);

    int t = threadIdx.x;
    int lane = t & 31, wid = t >> 5;
    int gid = lane >> 2, tg = lane & 3;
    int warpM = wid >> 1, warpN = wid & 1;
    int m0 = blockIdx.x * 128, bh = blockIdx.z;
    int bb = bh >> 3, h = bh & 7;

    const float* A = attn + (size_t)bh * L_ * L_;
    const float* V = g_v + (size_t)bh * L_ * E_;

    float acc[2][4][4] = {};

    auto stage = [&](int kt, int buf) {
        int k0 = kt * 32;
#pragma unroll
        for (int i = 0; i < 4; i++) {
            int idx = t + i * 256;            // attn 128x32
            int row = idx >> 3, cc = (idx & 7) * 4;
            cp16(sA + (buf * AV_AS + row * 36 + cc) * 4,
                 A + (size_t)(m0 + row) * L_ + k0 + cc);
        }
#pragma unroll
        for (int i = 0; i < 2; i++) {
            int idx = t + i * 256;            // V 32x64
            int row = idx >> 4, cc = (idx & 15) * 4;
            cp16(sB + (buf * AV_BS + row * 72 + cc) * 4,
                 V + (size_t)(k0 + row) * E_ + cc);
        }
    };

    const int NIT = L_ / 32;                  // 64
    stage(0, 0); CP_COMMIT();
    stage(1, 1); CP_COMMIT();
    for (int kt = 0; kt < NIT; kt++) {
        __syncthreads();
        if (kt + 2 < NIT) { stage(kt + 2, (kt + 2) % 3); CP_COMMIT(); CP_WAIT(2); }
        else if (kt + 1 < NIT) { CP_WAIT(1); }
        else { CP_WAIT(0); }
        __syncthreads();

        int p = kt % 3;
        const float* Ab = As + p * AV_AS;
        const float* Bb = Bs + p * AV_BS;
#pragma unroll
        for (int ks = 0; ks < 4; ks++) {
            int k0 = ks * 8;
            uint32_t ah[2][4], al[2][4], bh4[4][2], bl4[4][2];
#pragma unroll
            for (int mt = 0; mt < 2; mt++) {
                const float* pa = Ab + (warpM * 32 + mt * 16 + gid) * 36 + k0 + tg;
                split2(pa[0],          ah[mt][0], al[mt][0]);
                split2(pa[8 * 36],     ah[mt][1], al[mt][1]);
                split2(pa[4],          ah[mt][2], al[mt][2]);
                split2(pa[8 * 36 + 4], ah[mt][3], al[mt][3]);
            }
#pragma unroll
            for (int nt = 0; nt < 4; nt++) {
                const float* pb = Bb + (k0 + tg) * 72 + warpN * 32 + nt * 8 + gid;
                split2(pb[0],      bh4[nt][0], bl4[nt][0]);
                split2(pb[4 * 72], bh4[nt][1], bl4[nt][1]);
            }
#pragma unroll
            for (int mt = 0; mt < 2; mt++)
#pragma unroll
                for (int nt = 0; nt < 4; nt++) {
                    mma_tf32(acc[mt][nt], al[mt], bh4[nt]);
                    mma_tf32(acc[mt][nt], ah[mt], bl4[nt]);
                    mma_tf32(acc[mt][nt], ah[mt], bh4[nt]);
                }
        }
    }

#pragma unroll
    for (int mt = 0; mt < 2; mt++) {
        int r = m0 + warpM * 32 + mt * 16 + gid;
#pragma unroll
        for (int nt = 0; nt < 4; nt++) {
            int cc = warpN * 32 + nt * 8 + tg * 2;
            *reinterpret_cast<float2*>(out + ((size_t)(bb * L_ + r)) * D_ + h * 64 + cc) =
                make_float2(acc[mt][nt][0], acc[mt][nt][1]);
            *reinterpret_cast<float2*>(out + ((size_t)(bb * L_ + r + 8)) * D_ + h * 64 + cc) =
                make_float2(acc[mt][nt][2], acc[mt][nt][3]);
        }
    }
}

// ---------------------------------------------------------------------------
extern "C" void kernel_launch(void* const* d_in, const int* in_sizes, int n_in,
                              void* d_out, int out_size)
{
    const float* queries = (const float*)d_in[0];
    const float* keys    = (const float*)d_in[1];
    const float* values  = (const float*)d_in[2];
    const float* Wq      = (const float*)d_in[3];
    const float* bq      = (const float*)d_in[4];
    const float* Wk      = (const float*)d_in[5];
    const float* bk      = (const float*)d_in[6];
    const float* Wv      = (const float*)d_in[7];
    const float* bv      = (const float*)d_in[8];

    float* out  = (float*)d_out;
    float* attn = out + (size_t)B_ * L_ * D_;   // tuple order: (out, attn)

    static bool attr_set = false;
    if (!attr_set) {
        cudaFuncSetAttribute(proj_mma,   cudaFuncAttributeMaxDynamicSharedMemorySize, PJ_SMEM);
        cudaFuncSetAttribute(projv_mma3, cudaFuncAttributeMaxDynamicSharedMemorySize, PV_SMEM);
        cudaFuncSetAttribute(scores_mma, cudaFuncAttributeMaxDynamicSharedMemorySize, S_SMEM);
        cudaFuncSetAttribute(av_mma3,    cudaFuncAttributeMaxDynamicSharedMemorySize, AV_SMEM);
        attr_set = true;
    }

    proj_mma<<<dim3((B_ * L_) / 128, D_ / 128, 2), 256, PJ_SMEM>>>(
        queries, keys, Wq, Wk, bq, bk);
    projv_mma3<<<dim3((B_ * L_) / 128, D_ / 64), 256, PV_SMEM>>>(values, Wv, bv);
    scores_mma<<<dim3(L_ / 128, L_ / 128, B_ * H_), 256, S_SMEM>>>(attn);
    softmax_kernel<<<dim3(B_ * H_ * L_), 256>>>(attn);
    av_mma3<<<dim3(L_ / 128, 1, B_ * H_), 256, AV_SMEM>>>(attn, out);
}

// round 5
// speedup vs baseline: 1.2103x; 1.2103x over previous
#include <cuda_runtime.h>
#include <cstdint>

#define B_ 4
#define L_ 2048
#define D_ 512
#define H_ 8
#define E_ 64

// Projected Q/K/V scratch, [B,H,L,E] (each (b,h) slice is contiguous [L,E]).
__device__ __align__(256) float g_q[B_ * H_ * L_ * E_];
__device__ __align__(256) float g_k[B_ * H_ * L_ * E_];
__device__ __align__(256) float g_v[B_ * H_ * L_ * E_];
// Per-row partial sums of exp(scores): [row_global][col_tile 0..15]
__device__ __align__(256) float g_psum[B_ * H_ * L_ * 16];

// ---------------------------------------------------------------------------
// helpers
// ---------------------------------------------------------------------------
__device__ __forceinline__ uint32_t smem_u32(const void* p) {
    uint32_t a;
    asm("{ .reg .u64 t; cvta.to.shared.u64 t, %1; cvt.u32.u64 %0, t; }"
        : "=r"(a) : "l"(p));
    return a;
}

// D = A(16x8,row) * B(8x8,col) + D, tf32 inputs (raw f32 bits, HW truncates)
__device__ __forceinline__ void mma_tf32(float* d, const uint32_t* a, const uint32_t* b) {
    asm volatile(
        "mma.sync.aligned.m16n8k8.row.col.f32.tf32.tf32.f32 "
        "{%0,%1,%2,%3}, {%4,%5,%6,%7}, {%8,%9}, {%0,%1,%2,%3};"
        : "+f"(d[0]), "+f"(d[1]), "+f"(d[2]), "+f"(d[3])
        : "r"(a[0]), "r"(a[1]), "r"(a[2]), "r"(a[3]), "r"(b[0]), "r"(b[1]));
}

// 3xTF32 split: x = hi + lo, hi exactly representable in tf32.
__device__ __forceinline__ void split2(float x, uint32_t& hi, uint32_t& lo) {
    uint32_t xb = __float_as_uint(x);
    hi = xb & 0xFFFFE000u;
    lo = __float_as_uint(x - __uint_as_float(hi));
}

__device__ __forceinline__ void cp16(uint32_t dst, const void* src) {
    asm volatile("cp.async.cg.shared.global [%0], [%1], 16;"
                 :: "r"(dst), "l"(src) : "memory");
}
#define CP_COMMIT() asm volatile("cp.async.commit_group;" ::: "memory")
#define CP_WAIT(n)  asm volatile("cp.async.wait_group %0;" :: "n"(n) : "memory")

// ---------------------------------------------------------------------------
// Kernel 1a: Q/K projection (1x tf32).  CTA 128x128, 8 warps (2M x 4N),
// K=512 in BK=32 chunks, cp.async double buffer.  grid (64, 4, 2), 256 thr.
// ---------------------------------------------------------------------------
static constexpr int PJ_XS = 128 * 36;
static constexpr int PJ_WS = 32 * 136;
static constexpr int PJ_SMEM = (2 * PJ_XS + 2 * PJ_WS) * 4;   // 71680 B

__global__ void __launch_bounds__(256) proj_mma(
    const float* __restrict__ X0, const float* __restrict__ X1,
    const float* __restrict__ W0, const float* __restrict__ W1,
    const float* __restrict__ b0, const float* __restrict__ b1)
{
    extern __shared__ float smf[];
    float* Xs = smf;
    float* Ws = smf + 2 * PJ_XS;
    uint32_t sX = smem_u32(Xs), sW = smem_u32(Ws);

    int z = blockIdx.z;
    const float* X = z ? X1 : X0;
    const float* W = z ? W1 : W0;
    const float* bias = z ? b1 : b0;
    float* dst = z ? g_k : g_q;

    int t = threadIdx.x;
    int lane = t & 31, wid = t >> 5;
    int gid = lane >> 2, tg = lane & 3;
    int warpM = wid >> 2, warpN = wid & 3;
    int m0 = blockIdx.x * 128, n0 = blockIdx.y * 128;

    float acc[4][4][4] = {};

    auto stage = [&](int kt, int buf) {
        int k0 = kt * 32;
#pragma unroll
        for (int i = 0; i < 4; i++) {
            int idx = t + i * 256;
            int row = idx >> 3, cc = (idx & 7) * 4;
            cp16(sX + (buf * PJ_XS + row * 36 + cc) * 4,
                 X + (size_t)(m0 + row) * D_ + k0 + cc);
        }
#pragma unroll
        for (int i = 0; i < 4; i++) {
            int idx = t + i * 256;
            int row = idx >> 5, cc = (idx & 31) * 4;
            cp16(sW + (buf * PJ_WS + row * 136 + cc) * 4,
                 W + (size_t)(k0 + row) * D_ + n0 + cc);
        }
    };

    stage(0, 0); CP_COMMIT();
    const int NIT = D_ / 32;                 // 16
    for (int kt = 0; kt < NIT; kt++) {
        int p = kt & 1;
        if (kt + 1 < NIT) { stage(kt + 1, p ^ 1); CP_COMMIT(); CP_WAIT(1); }
        else              { CP_WAIT(0); }
        __syncthreads();

        const float* Ab = Xs + p * PJ_XS;
        const float* Bb = Ws + p * PJ_WS;
#pragma unroll
        for (int ks = 0; ks < 4; ks++) {
            int k0 = ks * 8;
            uint32_t a[4][4], b[4][2];
#pragma unroll
            for (int mt = 0; mt < 4; mt++) {
                const float* pa = Ab + (warpM * 64 + mt * 16 + gid) * 36 + k0 + tg;
                a[mt][0] = __float_as_uint(pa[0]);
                a[mt][1] = __float_as_uint(pa[8 * 36]);
                a[mt][2] = __float_as_uint(pa[4]);
                a[mt][3] = __float_as_uint(pa[8 * 36 + 4]);
            }
#pragma unroll
            for (int nt = 0; nt < 4; nt++) {
                const float* pb = Bb + (k0 + tg) * 136 + warpN * 32 + nt * 8 + gid;
                b[nt][0] = __float_as_uint(pb[0]);
                b[nt][1] = __float_as_uint(pb[4 * 136]);
            }
#pragma unroll
            for (int mt = 0; mt < 4; mt++)
#pragma unroll
                for (int nt = 0; nt < 4; nt++)
                    mma_tf32(acc[mt][nt], a[mt], b[nt]);
        }
        __syncthreads();
    }

#pragma unroll
    for (int mt = 0; mt < 4; mt++) {
        int m = m0 + warpM * 64 + mt * 16 + gid;
        int bb = m >> 11;
        int l  = m & (L_ - 1);
#pragma unroll
        for (int nt = 0; nt < 4; nt++) {
            int n = n0 + warpN * 32 + nt * 8 + tg * 2;
            int h = n >> 6, e = n & 63;
            float2 bi = *reinterpret_cast<const float2*>(bias + n);
            *reinterpret_cast<float2*>(dst + (((size_t)(bb * H_ + h)) * L_ + l) * E_ + e) =
                make_float2(acc[mt][nt][0] + bi.x, acc[mt][nt][1] + bi.y);
            *reinterpret_cast<float2*>(dst + (((size_t)(bb * H_ + h)) * L_ + l + 8) * E_ + e) =
                make_float2(acc[mt][nt][2] + bi.x, acc[mt][nt][3] + bi.y);
        }
    }
}

// ---------------------------------------------------------------------------
// Kernel 1b: V projection, 3xTF32.  CTA 128x64, 8 warps (4M x 2N),
// K=512 in BK=32 chunks, 3-stage cp.async pipeline.  grid (64, 8), 256 thr.
// ---------------------------------------------------------------------------
static constexpr int PV_XS = 128 * 36;
static constexpr int PV_WS = 32 * 72;
static constexpr int PV_SMEM = (3 * PV_XS + 3 * PV_WS) * 4;   // 82944 B

__global__ void __launch_bounds__(256, 2) projv_mma3(
    const float* __restrict__ X, const float* __restrict__ W,
    const float* __restrict__ bias)
{
    extern __shared__ float smf[];
    float* Xs = smf;
    float* Ws = smf + 3 * PV_XS;
    uint32_t sX = smem_u32(Xs), sW = smem_u32(Ws);

    int t = threadIdx.x;
    int lane = t & 31, wid = t >> 5;
    int gid = lane >> 2, tg = lane & 3;
    int warpM = wid >> 1, warpN = wid & 1;
    int m0 = blockIdx.x * 128, n0 = blockIdx.y * 64;

    float acc[2][4][4] = {};

    auto stage = [&](int kt, int buf) {
        int k0 = kt * 32;
#pragma unroll
        for (int i = 0; i < 4; i++) {
            int idx = t + i * 256;
            int row = idx >> 3, cc = (idx & 7) * 4;
            cp16(sX + (buf * PV_XS + row * 36 + cc) * 4,
                 X + (size_t)(m0 + row) * D_ + k0 + cc);
        }
#pragma unroll
        for (int i = 0; i < 2; i++) {
            int idx = t + i * 256;
            int row = idx >> 4, cc = (idx & 15) * 4;
            cp16(sW + (buf * PV_WS + row * 72 + cc) * 4,
                 W + (size_t)(k0 + row) * D_ + n0 + cc);
        }
    };

    const int NIT = D_ / 32;                  // 16
    stage(0, 0); CP_COMMIT();
    stage(1, 1); CP_COMMIT();
    for (int kt = 0; kt < NIT; kt++) {
        __syncthreads();
        if (kt + 2 < NIT) { stage(kt + 2, (kt + 2) % 3); CP_COMMIT(); CP_WAIT(2); }
        else if (kt + 1 < NIT) { CP_WAIT(1); }
        else { CP_WAIT(0); }
        __syncthreads();

        int p = kt % 3;
        const float* Ab = Xs + p * PV_XS;
        const float* Bb = Ws + p * PV_WS;
#pragma unroll
        for (int ks = 0; ks < 4; ks++) {
            int k0 = ks * 8;
            uint32_t ah[2][4], al[2][4], bh[4][2], bl[4][2];
#pragma unroll
            for (int mt = 0; mt < 2; mt++) {
                const float* pa = Ab + (warpM * 32 + mt * 16 + gid) * 36 + k0 + tg;
                split2(pa[0],           ah[mt][0], al[mt][0]);
                split2(pa[8 * 36],      ah[mt][1], al[mt][1]);
                split2(pa[4],           ah[mt][2], al[mt][2]);
                split2(pa[8 * 36 + 4],  ah[mt][3], al[mt][3]);
            }
#pragma unroll
            for (int nt = 0; nt < 4; nt++) {
                const float* pb = Bb + (k0 + tg) * 72 + warpN * 32 + nt * 8 + gid;
                split2(pb[0],      bh[nt][0], bl[nt][0]);
                split2(pb[4 * 72], bh[nt][1], bl[nt][1]);
            }
#pragma unroll
            for (int mt = 0; mt < 2; mt++)
#pragma unroll
                for (int nt = 0; nt < 4; nt++) {
                    mma_tf32(acc[mt][nt], al[mt], bh[nt]);
                    mma_tf32(acc[mt][nt], ah[mt], bl[nt]);
                    mma_tf32(acc[mt][nt], ah[mt], bh[nt]);
                }
        }
    }

#pragma unroll
    for (int mt = 0; mt < 2; mt++) {
        int m = m0 + warpM * 32 + mt * 16 + gid;
        int bb = m >> 11;
        int l  = m & (L_ - 1);
#pragma unroll
        for (int nt = 0; nt < 4; nt++) {
            int n = n0 + warpN * 32 + nt * 8 + tg * 2;
            int h = n >> 6, e = n & 63;
            float2 bi = *reinterpret_cast<const float2*>(bias + n);
            *reinterpret_cast<float2*>(g_v + (((size_t)(bb * H_ + h)) * L_ + l) * E_ + e) =
                make_float2(acc[mt][nt][0] + bi.x, acc[mt][nt][1] + bi.y);
            *reinterpret_cast<float2*>(g_v + (((size_t)(bb * H_ + h)) * L_ + l + 8) * E_ + e) =
                make_float2(acc[mt][nt][2] + bi.x, acc[mt][nt][3] + bi.y);
        }
    }
}

// ---------------------------------------------------------------------------
// Kernel 2: scores + exp.  Writes p = exp(scale * Q K^T) (unnormalized) into
// attn, and per-(row, col-tile) partial sums into g_psum.
// CTA 128x128 output tile, full K=64 resident.  grid (16,16,32), 256 threads.
// SMEM: Qs[128][68], Ks[128][68], red[4][128]
// ---------------------------------------------------------------------------
static constexpr int S_SMEM = (2 * 128 * 68 + 4 * 128) * 4;   // 71680 B

__global__ void __launch_bounds__(256) scores_mma(float* __restrict__ attn)
{
    extern __shared__ float smf[];
    float* Qs = smf;
    float* Ks = smf + 128 * 68;
    float* red = smf + 2 * 128 * 68;         // [4][128]

    int t = threadIdx.x;
    int lane = t & 31, wid = t >> 5;
    int gid = lane >> 2, tg = lane & 3;
    int warpM = wid >> 2, warpN = wid & 3;
    int m0 = blockIdx.x * 128, n0 = blockIdx.y * 128, bh = blockIdx.z;

    const float* Q = g_q + (size_t)bh * L_ * E_;
    const float* K = g_k + (size_t)bh * L_ * E_;
    float* S = attn + (size_t)bh * L_ * L_;

#pragma unroll
    for (int i = 0; i < 8; i++) {
        int idx = t + i * 256;
        int row = idx >> 4, cc = (idx & 15) * 4;
        *reinterpret_cast<float4*>(Qs + row * 68 + cc) =
            *reinterpret_cast<const float4*>(Q + (size_t)(m0 + row) * E_ + cc);
        *reinterpret_cast<float4*>(Ks + row * 68 + cc) =
            *reinterpret_cast<const float4*>(K + (size_t)(n0 + row) * E_ + cc);
    }
    __syncthreads();

    float acc[4][4][4] = {};
#pragma unroll
    for (int ks = 0; ks < 8; ks++) {
        int k0 = ks * 8;
        uint32_t a[4][4], b[4][2];
#pragma unroll
        for (int mt = 0; mt < 4; mt++) {
            const float* pa = Qs + (warpM * 64 + mt * 16 + gid) * 68 + k0 + tg;
            a[mt][0] = __float_as_uint(pa[0]);
            a[mt][1] = __float_as_uint(pa[8 * 68]);
            a[mt][2] = __float_as_uint(pa[4]);
            a[mt][3] = __float_as_uint(pa[8 * 68 + 4]);
        }
#pragma unroll
        for (int nt = 0; nt < 4; nt++) {
            const float* pb = Ks + (warpN * 32 + nt * 8 + gid) * 68 + k0 + tg;
            b[nt][0] = __float_as_uint(pb[0]);
            b[nt][1] = __float_as_uint(pb[4]);
        }
#pragma unroll
        for (int mt = 0; mt < 4; mt++)
#pragma unroll
            for (int nt = 0; nt < 4; nt++)
                mma_tf32(acc[mt][nt], a[mt], b[nt]);
    }

    const float scale = 0.125f;
    float rowpart[4][2] = {};                 // [mt][half]
#pragma unroll
    for (int mt = 0; mt < 4; mt++) {
        int r = m0 + warpM * 64 + mt * 16 + gid;
#pragma unroll
        for (int nt = 0; nt < 4; nt++) {
            int cc = n0 + warpN * 32 + nt * 8 + tg * 2;
            float p0 = __expf(acc[mt][nt][0] * scale);
            float p1 = __expf(acc[mt][nt][1] * scale);
            float p2 = __expf(acc[mt][nt][2] * scale);
            float p3 = __expf(acc[mt][nt][3] * scale);
            *reinterpret_cast<float2*>(S + (size_t)r * L_ + cc) = make_float2(p0, p1);
            *reinterpret_cast<float2*>(S + (size_t)(r + 8) * L_ + cc) = make_float2(p2, p3);
            rowpart[mt][0] += p0 + p1;
            rowpart[mt][1] += p2 + p3;
        }
    }

    // reduce partial row sums: over tg lanes, then over warpN via SMEM
#pragma unroll
    for (int mt = 0; mt < 4; mt++) {
#pragma unroll
        for (int half = 0; half < 2; half++) {
            float v = rowpart[mt][half];
            v += __shfl_xor_sync(0xffffffffu, v, 1);
            v += __shfl_xor_sync(0xffffffffu, v, 2);
            if (tg == 0)
                red[warpN * 128 + warpM * 64 + mt * 16 + gid + half * 8] = v;
        }
    }
    __syncthreads();
    if (t < 128) {
        float s = red[t] + red[128 + t] + red[256 + t] + red[384 + t];
        g_psum[((size_t)bh * L_ + m0 + t) * 16 + blockIdx.y] = s;
    }
}

// ---------------------------------------------------------------------------
// Kernel 3: AV (3xTF32) fused with softmax-normalize.
// Reads unnormalized exp from attn, writes normalized attn back in place,
// computes out = (attn_norm @ V).  CTA 128x64 output, 3-stage cp.async.
// grid (16,1,32), 256 threads.
// SMEM: As[3][128][36], Bs[3][32][72], rowinv[128]
// ---------------------------------------------------------------------------
static constexpr int AV_AS = 128 * 36;
static constexpr int AV_BS = 32 * 72;
static constexpr int AV_SMEM = (3 * AV_AS + 3 * AV_BS + 128) * 4;   // 83456 B

__global__ void __launch_bounds__(256, 2) av_mma3(float* __restrict__ attn,
                                                  float* __restrict__ out)
{
    extern __shared__ float smf[];
    float* As = smf;
    float* Bs = smf + 3 * AV_AS;
    float* rowinv = smf + 3 * AV_AS + 3 * AV_BS;
    uint32_t sA = smem_u32(As), sB = smem_u32(Bs);

    int t = threadIdx.x;
    int lane = t & 31, wid = t >> 5;
    int gid = lane >> 2, tg = lane & 3;
    int warpM = wid >> 1, warpN = wid & 1;
    int m0 = blockIdx.x * 128, bh = blockIdx.z;
    int bb = bh >> 3, h = bh & 7;

    float* A = attn + (size_t)bh * L_ * L_;
    const float* V = g_v + (size_t)bh * L_ * E_;

    float acc[2][4][4] = {};

    auto stage = [&](int kt, int buf) {
        int k0 = kt * 32;
#pragma unroll
        for (int i = 0; i < 4; i++) {
            int idx = t + i * 256;            // attn 128x32
            int row = idx >> 3, cc = (idx & 7) * 4;
            cp16(sA + (buf * AV_AS + row * 36 + cc) * 4,
                 A + (size_t)(m0 + row) * L_ + k0 + cc);
        }
#pragma unroll
        for (int i = 0; i < 2; i++) {
            int idx = t + i * 256;            // V 32x64
            int row = idx >> 4, cc = (idx & 15) * 4;
            cp16(sB + (buf * AV_BS + row * 72 + cc) * 4,
                 V + (size_t)(k0 + row) * E_ + cc);
        }
    };

    const int NIT = L_ / 32;                  // 64
    stage(0, 0); CP_COMMIT();
    stage(1, 1); CP_COMMIT();

    // row sums -> 1/sum
    if (t < 128) {
        const float* pp = g_psum + ((size_t)bh * L_ + m0 + t) * 16;
        float s = 0.f;
#pragma unroll
        for (int j = 0; j < 16; j++) s += pp[j];
        rowinv[t] = 1.0f / s;
    }

    for (int kt = 0; kt < NIT; kt++) {
        __syncthreads();
        if (kt + 2 < NIT) { stage(kt + 2, (kt + 2) % 3); CP_COMMIT(); CP_WAIT(2); }
        else if (kt + 1 < NIT) { CP_WAIT(1); }
        else { CP_WAIT(0); }
        __syncthreads();

        int p = kt % 3;
        const float* Ab = As + p * AV_AS;
        const float* Bb = Bs + p * AV_BS;

        // normalized write-back of this attn tile (values stay unnormalized in
        // SMEM; the out epilogue applies 1/rowsum to the accumulators)
        {
            int k0 = kt * 32;
#pragma unroll
            for (int i = 0; i < 4; i++) {
                int idx = t + i * 256;
                int row = idx >> 3, cc = (idx & 7) * 4;
                float4 v = *reinterpret_cast<const float4*>(Ab + row * 36 + cc);
                float s = rowinv[row];
                v.x *= s; v.y *= s; v.z *= s; v.w *= s;
                *reinterpret_cast<float4*>(A + (size_t)(m0 + row) * L_ + k0 + cc) = v;
            }
        }

#pragma unroll
        for (int ks = 0; ks < 4; ks++) {
            int k0 = ks * 8;
            uint32_t ah[2][4], al[2][4], bh4[4][2], bl4[4][2];
#pragma unroll
            for (int mt = 0; mt < 2; mt++) {
                const float* pa = Ab + (warpM * 32 + mt * 16 + gid) * 36 + k0 + tg;
                split2(pa[0],          ah[mt][0], al[mt][0]);
                split2(pa[8 * 36],     ah[mt][1], al[mt][1]);
                split2(pa[4],          ah[mt][2], al[mt][2]);
                split2(pa[8 * 36 + 4], ah[mt][3], al[mt][3]);
            }
#pragma unroll
            for (int nt = 0; nt < 4; nt++) {
                const float* pb = Bb + (k0 + tg) * 72 + warpN * 32 + nt * 8 + gid;
                split2(pb[0],      bh4[nt][0], bl4[nt][0]);
                split2(pb[4 * 72], bh4[nt][1], bl4[nt][1]);
            }
#pragma unroll
            for (int mt = 0; mt < 2; mt++)
#pragma unroll
                for (int nt = 0; nt < 4; nt++) {
                    mma_tf32(acc[mt][nt], al[mt], bh4[nt]);
                    mma_tf32(acc[mt][nt], ah[mt], bl4[nt]);
                    mma_tf32(acc[mt][nt], ah[mt], bh4[nt]);
                }
        }
    }

#pragma unroll
    for (int mt = 0; mt < 2; mt++) {
        int rloc = warpM * 32 + mt * 16 + gid;
        int r = m0 + rloc;
        float s0 = rowinv[rloc], s1 = rowinv[rloc + 8];
#pragma unroll
        for (int nt = 0; nt < 4; nt++) {
            int cc = warpN * 32 + nt * 8 + tg * 2;
            *reinterpret_cast<float2*>(out + ((size_t)(bb * L_ + r)) * D_ + h * 64 + cc) =
                make_float2(acc[mt][nt][0] * s0, acc[mt][nt][1] * s0);
            *reinterpret_cast<float2*>(out + ((size_t)(bb * L_ + r + 8)) * D_ + h * 64 + cc) =
                make_float2(acc[mt][nt][2] * s1, acc[mt][nt][3] * s1);
        }
    }
}

// ---------------------------------------------------------------------------
extern "C" void kernel_launch(void* const* d_in, const int* in_sizes, int n_in,
                              void* d_out, int out_size)
{
    const float* queries = (const float*)d_in[0];
    const float* keys    = (const float*)d_in[1];
    const float* values  = (const float*)d_in[2];
    const float* Wq      = (const float*)d_in[3];
    const float* bq      = (const float*)d_in[4];
    const float* Wk      = (const float*)d_in[5];
    const float* bk      = (const float*)d_in[6];
    const float* Wv      = (const float*)d_in[7];
    const float* bv      = (const float*)d_in[8];

    float* out  = (float*)d_out;
    float* attn = out + (size_t)B_ * L_ * D_;   // tuple order: (out, attn)

    static bool attr_set = false;
    if (!attr_set) {
        cudaFuncSetAttribute(proj_mma,   cudaFuncAttributeMaxDynamicSharedMemorySize, PJ_SMEM);
        cudaFuncSetAttribute(projv_mma3, cudaFuncAttributeMaxDynamicSharedMemorySize, PV_SMEM);
        cudaFuncSetAttribute(scores_mma, cudaFuncAttributeMaxDynamicSharedMemorySize, S_SMEM);
        cudaFuncSetAttribute(av_mma3,    cudaFuncAttributeMaxDynamicSharedMemorySize, AV_SMEM);
        attr_set = true;
    }

    proj_mma<<<dim3((B_ * L_) / 128, D_ / 128, 2), 256, PJ_SMEM>>>(
        queries, keys, Wq, Wk, bq, bk);
    projv_mma3<<<dim3((B_ * L_) / 128, D_ / 64), 256, PV_SMEM>>>(values, Wv, bv);
    scores_mma<<<dim3(L_ / 128, L_ / 128, B_ * H_), 256, S_SMEM>>>(attn);
    av_mma3<<<dim3(L_ / 128, 1, B_ * H_), 256, AV_SMEM>>>(attn, out);
}

// round 6
// speedup vs baseline: 1.5827x; 1.3077x over previous
#include <cuda_runtime.h>
#include <cstdint>

#define B_ 4
#define L_ 2048
#define D_ 512
#define H_ 8
#define E_ 64

// Projected Q/K/V scratch, [B,H,L,E] (each (b,h) slice is contiguous [L,E]).
__device__ __align__(256) float g_q[B_ * H_ * L_ * E_];
__device__ __align__(256) float g_k[B_ * H_ * L_ * E_];
__device__ __align__(256) float g_v[B_ * H_ * L_ * E_];
// Per-row partial sums of exp(scores): [row_global][col_tile 0..15]
__device__ __align__(256) float g_psum[B_ * H_ * L_ * 16];

// ---------------------------------------------------------------------------
// helpers
// ---------------------------------------------------------------------------
__device__ __forceinline__ uint32_t smem_u32(const void* p) {
    uint32_t a;
    asm("{ .reg .u64 t; cvta.to.shared.u64 t, %1; cvt.u32.u64 %0, t; }"
        : "=r"(a) : "l"(p));
    return a;
}

// Round fp32 -> nearest tf32 (kills the truncation bias of the MMA datapath).
__device__ __forceinline__ uint32_t rna(float x) {
    uint32_t r;
    asm("cvt.rna.tf32.f32 %0, %1;" : "=r"(r) : "f"(x));
    return r;
}

// D = A(16x8,row) * B(8x8,col) + D, tf32 inputs
__device__ __forceinline__ void mma_tf32(float* d, const uint32_t* a, const uint32_t* b) {
    asm volatile(
        "mma.sync.aligned.m16n8k8.row.col.f32.tf32.tf32.f32 "
        "{%0,%1,%2,%3}, {%4,%5,%6,%7}, {%8,%9}, {%0,%1,%2,%3};"
        : "+f"(d[0]), "+f"(d[1]), "+f"(d[2]), "+f"(d[3])
        : "r"(a[0]), "r"(a[1]), "r"(a[2]), "r"(a[3]), "r"(b[0]), "r"(b[1]));
}

__device__ __forceinline__ void cp16(uint32_t dst, const void* src) {
    asm volatile("cp.async.cg.shared.global [%0], [%1], 16;"
                 :: "r"(dst), "l"(src) : "memory");
}
#define CP_COMMIT() asm volatile("cp.async.commit_group;" ::: "memory")
#define CP_WAIT(n)  asm volatile("cp.async.wait_group %0;" :: "n"(n) : "memory")

// ---------------------------------------------------------------------------
// Kernel 1: QKV projection (1x tf32, RN-rounded operands).
// CTA 128x128, 8 warps (2M x 4N), K=512 in BK=32 chunks, double buffer.
// grid (64, 4, 3), 256 thr.
// ---------------------------------------------------------------------------
static constexpr int PJ_XS = 128 * 36;
static constexpr int PJ_WS = 32 * 136;
static constexpr int PJ_SMEM = (2 * PJ_XS + 2 * PJ_WS) * 4;   // 71680 B

__global__ void __launch_bounds__(256) proj_mma(
    const float* __restrict__ X0, const float* __restrict__ X1,
    const float* __restrict__ X2,
    const float* __restrict__ W0, const float* __restrict__ W1,
    const float* __restrict__ W2,
    const float* __restrict__ b0, const float* __restrict__ b1,
    const float* __restrict__ b2)
{
    extern __shared__ float smf[];
    float* Xs = smf;
    float* Ws = smf + 2 * PJ_XS;
    uint32_t sX = smem_u32(Xs), sW = smem_u32(Ws);

    int z = blockIdx.z;
    const float* X = (z == 0) ? X0 : (z == 1) ? X1 : X2;
    const float* W = (z == 0) ? W0 : (z == 1) ? W1 : W2;
    const float* bias = (z == 0) ? b0 : (z == 1) ? b1 : b2;
    float* dst = (z == 0) ? g_q : (z == 1) ? g_k : g_v;

    int t = threadIdx.x;
    int lane = t & 31, wid = t >> 5;
    int gid = lane >> 2, tg = lane & 3;
    int warpM = wid >> 2, warpN = wid & 3;
    int m0 = blockIdx.x * 128, n0 = blockIdx.y * 128;

    float acc[4][4][4] = {};

    auto stage = [&](int kt, int buf) {
        int k0 = kt * 32;
#pragma unroll
        for (int i = 0; i < 4; i++) {
            int idx = t + i * 256;
            int row = idx >> 3, cc = (idx & 7) * 4;
            cp16(sX + (buf * PJ_XS + row * 36 + cc) * 4,
                 X + (size_t)(m0 + row) * D_ + k0 + cc);
        }
#pragma unroll
        for (int i = 0; i < 4; i++) {
            int idx = t + i * 256;
            int row = idx >> 5, cc = (idx & 31) * 4;
            cp16(sW + (buf * PJ_WS + row * 136 + cc) * 4,
                 W + (size_t)(k0 + row) * D_ + n0 + cc);
        }
    };

    stage(0, 0); CP_COMMIT();
    const int NIT = D_ / 32;                 // 16
    for (int kt = 0; kt < NIT; kt++) {
        int p = kt & 1;
        if (kt + 1 < NIT) { stage(kt + 1, p ^ 1); CP_COMMIT(); CP_WAIT(1); }
        else              { CP_WAIT(0); }
        __syncthreads();

        const float* Ab = Xs + p * PJ_XS;
        const float* Bb = Ws + p * PJ_WS;
#pragma unroll
        for (int ks = 0; ks < 4; ks++) {
            int k0 = ks * 8;
            uint32_t a[4][4], b[4][2];
#pragma unroll
            for (int mt = 0; mt < 4; mt++) {
                const float* pa = Ab + (warpM * 64 + mt * 16 + gid) * 36 + k0 + tg;
                a[mt][0] = rna(pa[0]);
                a[mt][1] = rna(pa[8 * 36]);
                a[mt][2] = rna(pa[4]);
                a[mt][3] = rna(pa[8 * 36 + 4]);
            }
#pragma unroll
            for (int nt = 0; nt < 4; nt++) {
                const float* pb = Bb + (k0 + tg) * 136 + warpN * 32 + nt * 8 + gid;
                b[nt][0] = rna(pb[0]);
                b[nt][1] = rna(pb[4 * 136]);
            }
#pragma unroll
            for (int mt = 0; mt < 4; mt++)
#pragma unroll
                for (int nt = 0; nt < 4; nt++)
                    mma_tf32(acc[mt][nt], a[mt], b[nt]);
        }
        __syncthreads();
    }

#pragma unroll
    for (int mt = 0; mt < 4; mt++) {
        int m = m0 + warpM * 64 + mt * 16 + gid;
        int bb = m >> 11;
        int l  = m & (L_ - 1);
#pragma unroll
        for (int nt = 0; nt < 4; nt++) {
            int n = n0 + warpN * 32 + nt * 8 + tg * 2;
            int h = n >> 6, e = n & 63;
            float2 bi = *reinterpret_cast<const float2*>(bias + n);
            *reinterpret_cast<float2*>(dst + (((size_t)(bb * H_ + h)) * L_ + l) * E_ + e) =
                make_float2(acc[mt][nt][0] + bi.x, acc[mt][nt][1] + bi.y);
            *reinterpret_cast<float2*>(dst + (((size_t)(bb * H_ + h)) * L_ + l + 8) * E_ + e) =
                make_float2(acc[mt][nt][2] + bi.x, acc[mt][nt][3] + bi.y);
        }
    }
}

// ---------------------------------------------------------------------------
// Kernel 2: scores + exp (1x tf32, RN-rounded).  Writes p = exp(scale*QK^T)
// (unnormalized) into attn, partial row sums into g_psum.
// CTA 128x128, full K=64 resident.  grid (16,16,32), 256 threads.
// ---------------------------------------------------------------------------
static constexpr int S_SMEM = (2 * 128 * 68 + 4 * 128) * 4;   // 71680 B

__global__ void __launch_bounds__(256) scores_mma(float* __restrict__ attn)
{
    extern __shared__ float smf[];
    float* Qs = smf;
    float* Ks = smf + 128 * 68;
    float* red = smf + 2 * 128 * 68;         // [4][128]

    int t = threadIdx.x;
    int lane = t & 31, wid = t >> 5;
    int gid = lane >> 2, tg = lane & 3;
    int warpM = wid >> 2, warpN = wid & 3;
    int m0 = blockIdx.x * 128, n0 = blockIdx.y * 128, bh = blockIdx.z;

    const float* Q = g_q + (size_t)bh * L_ * E_;
    const float* K = g_k + (size_t)bh * L_ * E_;
    float* S = attn + (size_t)bh * L_ * L_;

#pragma unroll
    for (int i = 0; i < 8; i++) {
        int idx = t + i * 256;
        int row = idx >> 4, cc = (idx & 15) * 4;
        *reinterpret_cast<float4*>(Qs + row * 68 + cc) =
            *reinterpret_cast<const float4*>(Q + (size_t)(m0 + row) * E_ + cc);
        *reinterpret_cast<float4*>(Ks + row * 68 + cc) =
            *reinterpret_cast<const float4*>(K + (size_t)(n0 + row) * E_ + cc);
    }
    __syncthreads();

    float acc[4][4][4] = {};
#pragma unroll
    for (int ks = 0; ks < 8; ks++) {
        int k0 = ks * 8;
        uint32_t a[4][4], b[4][2];
#pragma unroll
        for (int mt = 0; mt < 4; mt++) {
            const float* pa = Qs + (warpM * 64 + mt * 16 + gid) * 68 + k0 + tg;
            a[mt][0] = rna(pa[0]);
            a[mt][1] = rna(pa[8 * 68]);
            a[mt][2] = rna(pa[4]);
            a[mt][3] = rna(pa[8 * 68 + 4]);
        }
#pragma unroll
        for (int nt = 0; nt < 4; nt++) {
            const float* pb = Ks + (warpN * 32 + nt * 8 + gid) * 68 + k0 + tg;
            b[nt][0] = rna(pb[0]);
            b[nt][1] = rna(pb[4]);
        }
#pragma unroll
        for (int mt = 0; mt < 4; mt++)
#pragma unroll
            for (int nt = 0; nt < 4; nt++)
                mma_tf32(acc[mt][nt], a[mt], b[nt]);
    }

    const float scale = 0.125f;
    float rowpart[4][2] = {};                 // [mt][half]
#pragma unroll
    for (int mt = 0; mt < 4; mt++) {
        int r = m0 + warpM * 64 + mt * 16 + gid;
#pragma unroll
        for (int nt = 0; nt < 4; nt++) {
            int cc = n0 + warpN * 32 + nt * 8 + tg * 2;
            float p0 = __expf(acc[mt][nt][0] * scale);
            float p1 = __expf(acc[mt][nt][1] * scale);
            float p2 = __expf(acc[mt][nt][2] * scale);
            float p3 = __expf(acc[mt][nt][3] * scale);
            *reinterpret_cast<float2*>(S + (size_t)r * L_ + cc) = make_float2(p0, p1);
            *reinterpret_cast<float2*>(S + (size_t)(r + 8) * L_ + cc) = make_float2(p2, p3);
            rowpart[mt][0] += p0 + p1;
            rowpart[mt][1] += p2 + p3;
        }
    }

    // reduce partial row sums over tg lanes, then over warpN via SMEM
#pragma unroll
    for (int mt = 0; mt < 4; mt++) {
#pragma unroll
        for (int half = 0; half < 2; half++) {
            float v = rowpart[mt][half];
            v += __shfl_xor_sync(0xffffffffu, v, 1);
            v += __shfl_xor_sync(0xffffffffu, v, 2);
            if (tg == 0)
                red[warpN * 128 + warpM * 64 + mt * 16 + gid + half * 8] = v;
        }
    }
    __syncthreads();
    if (t < 128) {
        float s = red[t] + red[128 + t] + red[256 + t] + red[384 + t];
        g_psum[((size_t)bh * L_ + m0 + t) * 16 + blockIdx.y] = s;
    }
}

// ---------------------------------------------------------------------------
// Kernel 3: AV (1x tf32, RN-rounded) fused with softmax-normalize.
// Reads unnormalized exp from attn, writes normalized attn back in place,
// computes out = (attn_norm @ V).  CTA 128x64, 3-stage cp.async.
// grid (16,1,32), 256 threads.
// ---------------------------------------------------------------------------
static constexpr int AV_AS = 128 * 36;
static constexpr int AV_BS = 32 * 72;
static constexpr int AV_SMEM = (3 * AV_AS + 3 * AV_BS + 128) * 4;   // 83456 B

__global__ void __launch_bounds__(256, 2) av_mma(float* __restrict__ attn,
                                                 float* __restrict__ out)
{
    extern __shared__ float smf[];
    float* As = smf;
    float* Bs = smf + 3 * AV_AS;
    float* rowinv = smf + 3 * AV_AS + 3 * AV_BS;
    uint32_t sA = smem_u32(As), sB = smem_u32(Bs);

    int t = threadIdx.x;
    int lane = t & 31, wid = t >> 5;
    int gid = lane >> 2, tg = lane & 3;
    int warpM = wid >> 1, warpN = wid & 1;
    int m0 = blockIdx.x * 128, bh = blockIdx.z;
    int bb = bh >> 3, h = bh & 7;

    float* A = attn + (size_t)bh * L_ * L_;
    const float* V = g_v + (size_t)bh * L_ * E_;

    float acc[2][4][4] = {};

    auto stage = [&](int kt, int buf) {
        int k0 = kt * 32;
#pragma unroll
        for (int i = 0; i < 4; i++) {
            int idx = t + i * 256;            // attn 128x32
            int row = idx >> 3, cc = (idx & 7) * 4;
            cp16(sA + (buf * AV_AS + row * 36 + cc) * 4,
                 A + (size_t)(m0 + row) * L_ + k0 + cc);
        }
#pragma unroll
        for (int i = 0; i < 2; i++) {
            int idx = t + i * 256;            // V 32x64
            int row = idx >> 4, cc = (idx & 15) * 4;
            cp16(sB + (buf * AV_BS + row * 72 + cc) * 4,
                 V + (size_t)(k0 + row) * E_ + cc);
        }
    };

    const int NIT = L_ / 32;                  // 64
    stage(0, 0); CP_COMMIT();
    stage(1, 1); CP_COMMIT();

    // row sums -> 1/sum
    if (t < 128) {
        const float* pp = g_psum + ((size_t)bh * L_ + m0 + t) * 16;
        float s = 0.f;
#pragma unroll
        for (int j = 0; j < 16; j++) s += pp[j];
        rowinv[t] = 1.0f / s;
    }

    for (int kt = 0; kt < NIT; kt++) {
        __syncthreads();
        if (kt + 2 < NIT) { stage(kt + 2, (kt + 2) % 3); CP_COMMIT(); CP_WAIT(2); }
        else if (kt + 1 < NIT) { CP_WAIT(1); }
        else { CP_WAIT(0); }
        __syncthreads();

        int p = kt % 3;
        const float* Ab = As + p * AV_AS;
        const float* Bb = Bs + p * AV_BS;

        // normalized write-back of this attn tile (SMEM stays unnormalized;
        // the out epilogue applies 1/rowsum to the accumulators)
        {
            int k0 = kt * 32;
#pragma unroll
            for (int i = 0; i < 4; i++) {
                int idx = t + i * 256;
                int row = idx >> 3, cc = (idx & 7) * 4;
                float4 v = *reinterpret_cast<const float4*>(Ab + row * 36 + cc);
                float s = rowinv[row];
                v.x *= s; v.y *= s; v.z *= s; v.w *= s;
                *reinterpret_cast<float4*>(A + (size_t)(m0 + row) * L_ + k0 + cc) = v;
            }
        }

#pragma unroll
        for (int ks = 0; ks < 4; ks++) {
            int k0 = ks * 8;
            uint32_t a[2][4], b[4][2];
#pragma unroll
            for (int mt = 0; mt < 2; mt++) {
                const float* pa = Ab + (warpM * 32 + mt * 16 + gid) * 36 + k0 + tg;
                a[mt][0] = rna(pa[0]);
                a[mt][1] = rna(pa[8 * 36]);
                a[mt][2] = rna(pa[4]);
                a[mt][3] = rna(pa[8 * 36 + 4]);
            }
#pragma unroll
            for (int nt = 0; nt < 4; nt++) {
                const float* pb = Bb + (k0 + tg) * 72 + warpN * 32 + nt * 8 + gid;
                b[nt][0] = rna(pb[0]);
                b[nt][1] = rna(pb[4 * 72]);
            }
#pragma unroll
            for (int mt = 0; mt < 2; mt++)
#pragma unroll
                for (int nt = 0; nt < 4; nt++)
                    mma_tf32(acc[mt][nt], a[mt], b[nt]);
        }
    }

#pragma unroll
    for (int mt = 0; mt < 2; mt++) {
        int rloc = warpM * 32 + mt * 16 + gid;
        int r = m0 + rloc;
        float s0 = rowinv[rloc], s1 = rowinv[rloc + 8];
#pragma unroll
        for (int nt = 0; nt < 4; nt++) {
            int cc = warpN * 32 + nt * 8 + tg * 2;
            *reinterpret_cast<float2*>(out + ((size_t)(bb * L_ + r)) * D_ + h * 64 + cc) =
                make_float2(acc[mt][nt][0] * s0, acc[mt][nt][1] * s0);
            *reinterpret_cast<float2*>(out + ((size_t)(bb * L_ + r + 8)) * D_ + h * 64 + cc) =
                make_float2(acc[mt][nt][2] * s1, acc[mt][nt][3] * s1);
        }
    }
}

// ---------------------------------------------------------------------------
extern "C" void kernel_launch(void* const* d_in, const int* in_sizes, int n_in,
                              void* d_out, int out_size)
{
    const float* queries = (const float*)d_in[0];
    const float* keys    = (const float*)d_in[1];
    const float* values  = (const float*)d_in[2];
    const float* Wq      = (const float*)d_in[3];
    const float* bq      = (const float*)d_in[4];
    const float* Wk      = (const float*)d_in[5];
    const float* bk      = (const float*)d_in[6];
    const float* Wv      = (const float*)d_in[7];
    const float* bv      = (const float*)d_in[8];

    float* out  = (float*)d_out;
    float* attn = out + (size_t)B_ * L_ * D_;   // tuple order: (out, attn)

    static bool attr_set = false;
    if (!attr_set) {
        cudaFuncSetAttribute(proj_mma,   cudaFuncAttributeMaxDynamicSharedMemorySize, PJ_SMEM);
        cudaFuncSetAttribute(scores_mma, cudaFuncAttributeMaxDynamicSharedMemorySize, S_SMEM);
        cudaFuncSetAttribute(av_mma,     cudaFuncAttributeMaxDynamicSharedMemorySize, AV_SMEM);
        attr_set = true;
    }

    proj_mma<<<dim3((B_ * L_) / 128, D_ / 128, 3), 256, PJ_SMEM>>>(
        queries, keys, values, Wq, Wk, Wv, bq, bk, bv);
    scores_mma<<<dim3(L_ / 128, L_ / 128, B_ * H_), 256, S_SMEM>>>(attn);
    av_mma<<<dim3(L_ / 128, 1, B_ * H_), 256, AV_SMEM>>>(attn, out);
}